// round 6
// baseline (speedup 1.0000x reference)
#include <cuda_runtime.h>
#include <math.h>

// ---------------------------------------------------------------------------
// VanishingNet full pipeline, fp32. Pixel-major (NHWC) everywhere.
// ---------------------------------------------------------------------------

#define kB     2
#define kC     128
#define kNPIX  16384
#define kHTH   184
#define kHTW   180
#define kNBINS (kHTH * kHTW)   /* 33120 */
#define kSN    1984            /* per-batch node rows: 1024 + 768 + 192 */
#define kNR    (kB * kSN)      /* 3968 */
#define kEPS   1e-5f

// --------------------------- scratch (device globals) ----------------------
__device__ float g_xT [kB * kNPIX * kC];    // BN+ReLU image, [b][p][c]
__device__ float g_ht [kB * kNBINS * kC];   // Hough map, [b][bin][c]
__device__ float g_hc [kB * kNBINS * kC];   // conv out, [b][bin][c]
__device__ float g_sph[kNR * kC];           // sphere features [r][c]
__device__ float g_y  [kNR * 64];           // sconv pre-BN
__device__ float g_xa [kNR * 64];           // dgcn ping
__device__ float g_xb [kNR * 64];           // dgcn pong
__device__ float g_simg[2 * kC];            // image BN stats
__device__ float g_sht [2 * kC];            // ht BN stats (atomics)
__device__ float g_ssc [2 * 192];           // sconv BN stats (atomics)
__device__ float g_bce [12];                // {sum_pos,sum_neg,npos,nneg} x3

__device__ __forceinline__ float warpSum(float v) {
    #pragma unroll
    for (int o = 16; o > 0; o >>= 1) v += __shfl_down_sync(0xffffffffu, v, o);
    return v;
}
__device__ __forceinline__ float fcomp(const float4& a, int u) {
    return u == 0 ? a.x : (u == 1 ? a.y : (u == 2 ? a.z : a.w));
}

// --------------------------- k0: zero accumulators --------------------------
__global__ void k_zero() {
    int t = threadIdx.x;
    if (t < 2 * kC) { g_sht[t] = 0.f; }
    if (t < 384)    { g_ssc[t] = 0.f; }
    if (t < 12)     { g_bce[t] = 0.f; }
}

// --------------------------- k1: image BN stats ------------------------------
__global__ __launch_bounds__(256) void k_img_stats(const float* __restrict__ img) {
    int c = blockIdx.x, t = threadIdx.x;
    float s = 0.f, s2 = 0.f;
    for (int b = 0; b < kB; b++) {
        const float* p = img + (size_t)(b * kC + c) * kNPIX;
        for (int i = t; i < kNPIX; i += 256) { float v = p[i]; s += v; s2 += v * v; }
    }
    __shared__ float rs[8], rs2[8];
    int lane = t & 31, w = t >> 5;
    s = warpSum(s); s2 = warpSum(s2);
    if (lane == 0) { rs[w] = s; rs2[w] = s2; }
    __syncthreads();
    if (t == 0) {
        float a = 0.f, a2 = 0.f;
        #pragma unroll
        for (int i = 0; i < 8; i++) { a += rs[i]; a2 += rs2[i]; }
        g_simg[c] = a; g_simg[kC + c] = a2;
    }
}

// ---------------- k2: BN + ReLU + transpose to pixel-major -------------------
__global__ void k_bnt(const float* __restrict__ img, const float* __restrict__ gam,
                      const float* __restrict__ bet) {
    __shared__ float tile[32][33];
    int p0 = blockIdx.x * 32, c0 = blockIdx.y * 32, b = blockIdx.z;
    int tx = threadIdx.x, ty = threadIdx.y;
    #pragma unroll
    for (int i = 0; i < 4; i++) {
        int c = c0 + ty * 4 + i;
        tile[ty * 4 + i][tx] = img[(size_t)(b * kC + c) * kNPIX + p0 + tx];
    }
    __syncthreads();
    int c = c0 + tx;
    float mean = g_simg[c] * (1.f / 32768.f);
    float var  = g_simg[kC + c] * (1.f / 32768.f) - mean * mean;
    float sc = gam[c] * rsqrtf(var + kEPS);
    float bi = bet[c] - mean * sc;
    #pragma unroll
    for (int i = 0; i < 4; i++) {
        int p = p0 + ty * 4 + i;
        float v = tile[tx][ty * 4 + i];
        g_xT[(size_t)(b * kNPIX + p) * kC + c] = fmaxf(sc * v + bi, 0.f);
    }
}

// --------------------------- k3: Hough voting --------------------------------
__global__ __launch_bounds__(128) void k_hough(const int* __restrict__ hidx,
                                               const float* __restrict__ hw) {
    int bin = blockIdx.x, b = blockIdx.y, c = threadIdx.x;
    __shared__ int   sidx[8];
    __shared__ float swt[8];
    if (c < 8) { sidx[c] = hidx[bin * 8 + c]; swt[c] = hw[bin * 8 + c]; }
    __syncthreads();
    const float* xb = g_xT + (size_t)b * kNPIX * kC;
    float acc = 0.f;
    #pragma unroll
    for (int k = 0; k < 8; k++) acc += swt[k] * xb[(size_t)sidx[k] * kC + c];
    g_ht[(size_t)(b * kNBINS + bin) * kC + c] = acc;
}

// --------------------------- k4: 3x3 conv ------------------------------------
// Block: 64 px (one y row) x 128 cout. Thread: 8 px x 4 cout. cin chunks of 32.
__global__ __launch_bounds__(256, 2) void k_conv(const float* __restrict__ Wc) {
    __shared__ __align__(16) float sIn[3 * 66 * 32];  // [kh][px 0..65][ci]
    __shared__ __align__(16) float sW[32 * 128];      // [ci][co]
    const int t   = threadIdx.x;
    const int xc0 = blockIdx.x * 64;
    const int y   = blockIdx.y;
    const int b   = blockIdx.z;
    const int cog = t & 31;          // lane
    const int pg  = t >> 5;          // warp = pixel phase 0..7
    const int co0 = cog << 2;
    float acc[8][4];
    #pragma unroll
    for (int m = 0; m < 8; m++)
        #pragma unroll
        for (int j = 0; j < 4; j++) acc[m][j] = 0.f;

    for (int cc = 0; cc < 128; cc += 32) {
        __syncthreads();   // protect sIn from previous chunk's readers
        for (int i = t; i < 3 * 66 * 32; i += 256) {
            int ci = i & 31; int r2 = i >> 5; int px = r2 % 66; int kh = r2 / 66;
            int gy = y + kh - 1, gx = xc0 + px - 1;
            float v = 0.f;
            if ((unsigned)gy < kHTH && (unsigned)gx < kHTW)
                v = g_ht[(size_t)(b * kNBINS + gy * kHTW + gx) * kC + cc + ci];
            sIn[i] = v;
        }
        #pragma unroll 1
        for (int tap = 0; tap < 9; tap++) {
            __syncthreads();   // sIn ready / previous sW consumed
            const float* wp = Wc + (size_t)(tap * kC + cc) * kC;
            for (int i = t; i < 4096; i += 256) sW[i] = wp[i];
            __syncthreads();
            const int kh = tap / 3, kw = tap - kh * 3;
            const float* inRow = &sIn[(kh * 66 + kw + pg) * 32];
            #pragma unroll
            for (int c4 = 0; c4 < 8; c4++) {
                float4 A[8];
                #pragma unroll
                for (int m = 0; m < 8; m++)
                    A[m] = *reinterpret_cast<const float4*>(inRow + (m << 8) + (c4 << 2));
                #pragma unroll
                for (int u = 0; u < 4; u++) {
                    float4 w = *reinterpret_cast<const float4*>(&sW[(c4 * 4 + u) * 128 + co0]);
                    #pragma unroll
                    for (int m = 0; m < 8; m++) {
                        float a = fcomp(A[m], u);
                        acc[m][0] += a * w.x;
                        acc[m][1] += a * w.y;
                        acc[m][2] += a * w.z;
                        acc[m][3] += a * w.w;
                    }
                }
            }
        }
    }
    #pragma unroll
    for (int m = 0; m < 8; m++) {
        int gx = xc0 + pg + 8 * m;
        if (gx < kHTW) {
            float4 o = make_float4(acc[m][0], acc[m][1], acc[m][2], acc[m][3]);
            *reinterpret_cast<float4*>(
                &g_hc[(size_t)(b * kNBINS + y * kHTW + gx) * kC + co0]) = o;
        }
    }
}

// --------------------------- k5: ht BN stats ---------------------------------
__global__ __launch_bounds__(128) void k_htstats() {
    int t = threadIdx.x, blk = blockIdx.x;
    int r0 = blk * 130, r1 = min(r0 + 130, kB * kNBINS);
    float s = 0.f, s2 = 0.f;
    for (int r = r0; r < r1; r++) {
        float v = g_hc[(size_t)r * kC + t];
        s += v; s2 += v * v;
    }
    atomicAdd(&g_sht[t], s);
    atomicAdd(&g_sht[kC + t], s2);
}

// ---------------- k6: sphere gather (fused ht BN + ReLU) ---------------------
__global__ __launch_bounds__(128) void k_sphere(const float* __restrict__ gam,
                                                const float* __restrict__ bet,
                                                const int* __restrict__ sph_idx,
                                                const float* __restrict__ sph_w,
                                                const int* __restrict__ ind0,
                                                const int* __restrict__ ind1,
                                                const int* __restrict__ ind2) {
    int s = blockIdx.x, b = blockIdx.y, c = threadIdx.x;
    __shared__ int   sbin[16];
    __shared__ float swt[16];
    int sp;
    if (s < 1024)      sp = ind0[b * 1024 + s];
    else if (s < 1792) sp = ind1[b * 768 + (s - 1024)];
    else               sp = ind2[b * 192 + (s - 1792)];
    if (c < 16) { sbin[c] = sph_idx[sp * 16 + c]; swt[c] = sph_w[sp * 16 + c]; }
    __syncthreads();
    const float inv = 1.f / (float)(kB * kNBINS);
    float mean = g_sht[c] * inv;
    float var  = g_sht[kC + c] * inv - mean * mean;
    float sc = gam[c] * rsqrtf(var + kEPS);
    float bi = bet[c] - mean * sc;
    const float* base = g_hc + (size_t)b * kNBINS * kC;
    float acc = 0.f;
    #pragma unroll
    for (int k = 0; k < 16; k++)
        acc += swt[k] * fmaxf(sc * base[(size_t)sbin[k] * kC + c] + bi, 0.f);
    g_sph[(size_t)(b * kSN + s) * kC + c] = acc;
}

// --------------------------- k7: sconv (1x1 conv) + stats --------------------
__global__ __launch_bounds__(128) void k_sconv(const float* __restrict__ w_sc,
                                               const float* __restrict__ b_sc) {
    __shared__ float sWt[128 * 64];   // [c][o]
    __shared__ float sRow[2][128];
    int bx = blockIdx.x;
    int b = bx / 31, u = bx % 31;
    int sc, rbase;
    if (u < 16)      { sc = 0; rbase = b * kSN + u * 64; }
    else if (u < 28) { sc = 1; rbase = b * kSN + 1024 + (u - 16) * 64; }
    else             { sc = 2; rbase = b * kSN + 1792 + (u - 28) * 64; }
    int t = threadIdx.x, o = t & 63, half = t >> 6;
    for (int i = t; i < 8192; i += 128) {
        int c = i >> 6, oo = i & 63;
        sWt[i] = w_sc[(size_t)(sc * 64 + oo) * 128 + c];
    }
    __syncthreads();
    float bo = b_sc[sc * 64 + o];
    float ls = 0.f, ls2 = 0.f;
    for (int r0 = 0; r0 < 64; r0 += 2) {
        __syncthreads();
        sRow[0][t] = g_sph[(size_t)(rbase + r0) * 128 + t];
        sRow[1][t] = g_sph[(size_t)(rbase + r0 + 1) * 128 + t];
        __syncthreads();
        const float* rp = sRow[half];
        float acc = bo;
        #pragma unroll 8
        for (int c = 0; c < 128; c++) acc += rp[c] * sWt[c * 64 + o];
        g_y[(size_t)(rbase + r0 + half) * 64 + o] = acc;
        ls += acc; ls2 += acc * acc;
    }
    atomicAdd(&g_ssc[sc * 64 + o], ls);
    atomicAdd(&g_ssc[192 + sc * 64 + o], ls2);
}

// --------------------------- k8: sconv BN + ReLU -----------------------------
__global__ void k_scbn(const float* __restrict__ gam, const float* __restrict__ bet) {
    int idx = blockIdx.x * blockDim.x + threadIdx.x;
    if (idx >= kNR * 64) return;
    int r = idx >> 6, o = idx & 63;
    int s = r % kSN;
    int sc = (s < 1024) ? 0 : (s < 1792 ? 1 : 2);
    float cnt = (sc == 0) ? 2048.f : (sc == 1 ? 1536.f : 384.f);
    float mean = g_ssc[sc * 64 + o] / cnt;
    float var  = g_ssc[192 + sc * 64 + o] / cnt - mean * mean;
    float scv = gam[sc * 64 + o] * rsqrtf(var + kEPS);
    float bi  = bet[sc * 64 + o] - mean * scv;
    g_xa[idx] = fmaxf(scv * g_y[idx] + bi, 0.f);
}

// --------------------------- k9: one EdgeConv layer --------------------------
// Block = 256 threads = 4 nodes (64 threads each, one output channel per thread).
__global__ __launch_bounds__(256) void k_dgcn(const float* __restrict__ xin,
                                              float* __restrict__ xout,
                                              const float* __restrict__ W,
                                              const float* __restrict__ bias,
                                              const int* __restrict__ e0,
                                              const int* __restrict__ e1,
                                              const int* __restrict__ e2,
                                              int sc) {
    __shared__ __align__(16) float sW1[64 * 64];  // [c][o]: weight rows 0..63 (xc)
    __shared__ __align__(16) float sW2[64 * 64];  // rows 64..127 (xn - xc)
    __shared__ __align__(16) float sx[4][64], sn[4][64];
    int t = threadIdx.x;
    for (int i = t; i < 4096; i += 256) {
        sW1[i] = W[i];
        sW2[i] = W[4096 + i];
    }
    __syncthreads();
    int g64 = t >> 6, o = t & 63;
    int m = blockIdx.x * 4 + g64;

    int r, rbase, ecBase, enBase;
    const int* E;
    if (sc == 0) {
        int b = m >> 10, j = m & 1023;
        rbase = b * kSN; r = rbase + j;
        E = e0; ecBase = b * 2 * 8192 + j * 8; enBase = ecBase + 8192;
    } else if (sc == 1) {
        int g = m >> 8, j = m & 255;
        int b = g / 3, v = g - 3 * b;
        rbase = b * kSN + 1024 + v * 256; r = rbase + j;
        E = e1; ecBase = g * 2 * 2048 + j * 8; enBase = ecBase + 2048;
    } else {
        int g = m >> 6, j = m & 63;
        int b = g / 3, v = g - 3 * b;
        rbase = b * kSN + 1792 + v * 64; r = rbase + j;
        E = e2; ecBase = g * 2 * 512 + j * 8; enBase = ecBase + 512;
    }
    float bo = bias[o];
    float mv = -1e30f;
    #pragma unroll 1
    for (int kk = 0; kk < 8; kk++) {
        int ci = E[ecBase + kk], ni = E[enBase + kk];
        sx[g64][o] = xin[(size_t)(rbase + ci) * 64 + o];
        sn[g64][o] = xin[(size_t)(rbase + ni) * 64 + o];
        __syncthreads();
        float acc = bo;
        const float* px = sx[g64];
        const float* pn = sn[g64];
        #pragma unroll
        for (int c4 = 0; c4 < 16; c4++) {
            float4 a = *reinterpret_cast<const float4*>(&px[c4 * 4]);
            float4 n = *reinterpret_cast<const float4*>(&pn[c4 * 4]);
            int cb = c4 * 4;
            acc += a.x * sW1[(cb + 0) * 64 + o] + (n.x - a.x) * sW2[(cb + 0) * 64 + o];
            acc += a.y * sW1[(cb + 1) * 64 + o] + (n.y - a.y) * sW2[(cb + 1) * 64 + o];
            acc += a.z * sW1[(cb + 2) * 64 + o] + (n.z - a.z) * sW2[(cb + 2) * 64 + o];
            acc += a.w * sW1[(cb + 3) * 64 + o] + (n.w - a.w) * sW2[(cb + 3) * 64 + o];
        }
        mv = fmaxf(mv, fmaxf(acc, 0.f));
        __syncthreads();
    }
    xout[(size_t)r * 64 + o] = mv;
}

// --------------------------- k10: head + BCE accumulation --------------------
__global__ __launch_bounds__(256) void k_head(const float* __restrict__ hw,
                                              const float* __restrict__ hb,
                                              const int* __restrict__ t0,
                                              const int* __restrict__ t1,
                                              const int* __restrict__ t2,
                                              float* __restrict__ out) {
    int t = threadIdx.x;
    int warp = t >> 5, lane = t & 31;
    int r = blockIdx.x * 8 + warp;
    if (r >= kNR) return;
    int b = r / kSN, s = r - b * kSN;
    int sc, tgt;
    if (s < 1024)      { sc = 0; tgt = t0[b * 1024 + s]; }
    else if (s < 1792) { sc = 1; int q = s - 1024; tgt = t1[(b * 3 + (q >> 8)) * 256 + (q & 255)]; }
    else               { sc = 2; int q = s - 1792; tgt = t2[(b * 3 + (q >> 6)) * 64 + (q & 63)]; }
    const float* x = g_xa + (size_t)r * 64;
    float partial = x[lane] * hw[sc * 64 + lane] + x[lane + 32] * hw[sc * 64 + lane + 32];
    partial = warpSum(partial);
    if (lane == 0) {
        float z = partial + hb[sc];
        out[6 + r] = 1.f / (1.f + expf(-z));
        float l = fmaxf(z, 0.f) - z * (float)tgt + log1pf(expf(-fabsf(z)));
        if (tgt > 0) { atomicAdd(&g_bce[sc * 4 + 0], l); atomicAdd(&g_bce[sc * 4 + 2], 1.f); }
        else         { atomicAdd(&g_bce[sc * 4 + 1], l); atomicAdd(&g_bce[sc * 4 + 3], 1.f); }
    }
}

// --------------------------- k11: finalize losses ----------------------------
__global__ void k_final(float* __restrict__ out) {
    int sc = threadIdx.x;
    if (sc < 3) {
        float np = fmaxf(g_bce[sc * 4 + 2], 1.f);
        float nn = fmaxf(g_bce[sc * 4 + 3], 1.f);
        out[sc * 2 + 0] = g_bce[sc * 4 + 0] / np;
        out[sc * 2 + 1] = g_bce[sc * 4 + 1] / nn;
    }
}

// ---------------------------------------------------------------------------
extern "C" void kernel_launch(void* const* d_in, const int* in_sizes, int n_in,
                              void* d_out, int out_size) {
    const float* image      = (const float*)d_in[0];
    const float* bn_gamma   = (const float*)d_in[1];
    const float* bn_beta    = (const float*)d_in[2];
    const int*   ht_idx     = (const int*)  d_in[3];
    const float* ht_w       = (const float*)d_in[4];
    const float* w_htconv   = (const float*)d_in[5];
    const float* htbn_gamma = (const float*)d_in[6];
    const float* htbn_beta  = (const float*)d_in[7];
    const int*   sph_idx    = (const int*)  d_in[8];
    const float* sph_w      = (const float*)d_in[9];
    const float* w_sc       = (const float*)d_in[10];
    const float* b_sc       = (const float*)d_in[11];
    const float* scbn_gamma = (const float*)d_in[12];
    const float* scbn_beta  = (const float*)d_in[13];
    const float* dgcn_w     = (const float*)d_in[14];
    const float* dgcn_b     = (const float*)d_in[15];
    const float* dgcn_hw    = (const float*)d_in[16];
    const float* dgcn_hb    = (const float*)d_in[17];
    const int*   ind0       = (const int*)  d_in[18];
    const int*   ind1       = (const int*)  d_in[19];
    const int*   ind2       = (const int*)  d_in[20];
    const int*   edge0      = (const int*)  d_in[21];
    const int*   edge1      = (const int*)  d_in[22];
    const int*   edge2      = (const int*)  d_in[23];
    const int*   target0    = (const int*)  d_in[24];
    const int*   target1    = (const int*)  d_in[25];
    const int*   target2    = (const int*)  d_in[26];
    float* out = (float*)d_out;

    k_zero<<<1, 512>>>();
    k_img_stats<<<kC, 256>>>(image);
    k_bnt<<<dim3(kNPIX / 32, kC / 32, kB), dim3(32, 8)>>>(image, bn_gamma, bn_beta);
    k_hough<<<dim3(kNBINS, kB), 128>>>(ht_idx, ht_w);
    k_conv<<<dim3(3, kHTH, kB), 256>>>(w_htconv);
    k_htstats<<<510, 128>>>();
    k_sphere<<<dim3(kSN, kB), 128>>>(htbn_gamma, htbn_beta, sph_idx, sph_w,
                                     ind0, ind1, ind2);
    k_sconv<<<62, 128>>>(w_sc, b_sc);
    k_scbn<<<(kNR * 64 + 255) / 256, 256>>>(scbn_gamma, scbn_beta);

    // dgcn: 4 layers x 3 scales; ping-pong g_xa <-> g_xb (disjoint rows per scale)
    float* xa; float* xb;
    cudaGetSymbolAddress((void**)&xa, g_xa);
    cudaGetSymbolAddress((void**)&xb, g_xb);
    const int grids[3] = {2048 / 4, 1536 / 4, 384 / 4};
    float* pin = xa; float* pout = xb;
    for (int layer = 0; layer < 4; layer++) {
        for (int sc = 0; sc < 3; sc++) {
            k_dgcn<<<grids[sc], 256>>>(pin, pout,
                                       dgcn_w + (size_t)(sc * 4 + layer) * 128 * 64,
                                       dgcn_b + (size_t)(sc * 4 + layer) * 64,
                                       edge0, edge1, edge2, sc);
        }
        float* tmp = pin; pin = pout; pout = tmp;
    }
    // after 4 swaps the final features are back in g_xa (pin == xa)

    k_head<<<(kNR + 7) / 8, 256>>>(dgcn_hw, dgcn_hb, target0, target1, target2, out);
    k_final<<<1, 32>>>(out);
}